// round 16
// baseline (speedup 1.0000x reference)
#include <cuda_runtime.h>
#include <cuda_fp16.h>
#include <mma.h>
#include <cstdint>

using namespace nvcuda;

#define HID     128
#define M_TILE  128
#define THREADS 512
#define LDH     136     // half stride: 272B ≡ 16 mod 128 -> conflict-free LDSM

// Device globals (no cudaMalloc). Zero-initialized at module load.
__device__ float        g_agg[65536];   // re-zeroed by mlp after read each replay
__device__ unsigned int g_sync;         // monotonic grid-barrier ticket counter

// silu via single-MUFU tanh: sigmoid(x) = 0.5*tanh(x/2) + 0.5
__device__ __forceinline__ float silu(float x) {
    float t;
    asm("tanh.approx.f32 %0, %1;" : "=f"(t) : "f"(x * 0.5f));
    return x * (0.5f * t + 0.5f);
}
__device__ __forceinline__ uint32_t packh2f(float a, float b) {
    __half2 h = __floats2half2_rn(a, b);
    return *reinterpret_cast<uint32_t*>(&h);
}
__device__ __forceinline__ void cp_async16(void* dst_smem, const void* src, int src_sz) {
    unsigned d = (unsigned)__cvta_generic_to_shared(dst_smem);
    asm volatile("cp.async.cg.shared.global [%0], [%1], 16, %2;"
                 :: "r"(d), "l"(src), "r"(src_sz));
}
__device__ __forceinline__ void cp_commit() {
    asm volatile("cp.async.commit_group;" ::: "memory");
}
__device__ __forceinline__ void cp_wait0() {
    asm volatile("cp.async.wait_group 0;" ::: "memory");
}
// named barrier over one 128-thread row group (ids 1..4)
__device__ __forceinline__ void bar_group(int id) {
    asm volatile("bar.sync %0, 128;" :: "r"(id) : "memory");
}

using FragA = wmma::fragment<wmma::matrix_a, 16, 16, 16, __half, wmma::row_major>;
using FragB = wmma::fragment<wmma::matrix_b, 16, 16, 16, __half, wmma::row_major>;
using FragC = wmma::fragment<wmma::accumulator, 16, 16, 16, float>;

// acc[2][2] += A[r0..+31][0..127] @ B[0..127][c0..+31], fp16 smem, ping-pong.
__device__ __forceinline__ void gemm_fp16(const __half* __restrict__ as,
                                          const __half* __restrict__ bs,
                                          int r0, int c0, FragC acc[2][2]) {
    FragA af[2][2];
    FragB bf[2][2];
    wmma::load_matrix_sync(af[0][0], as + (size_t)r0 * LDH, LDH);
    wmma::load_matrix_sync(af[0][1], as + (size_t)(r0 + 16) * LDH, LDH);
    wmma::load_matrix_sync(bf[0][0], bs + c0, LDH);
    wmma::load_matrix_sync(bf[0][1], bs + c0 + 16, LDH);
#pragma unroll
    for (int ks = 0; ks < 8; ks++) {
        int cur = ks & 1, nxt = cur ^ 1;
        if (ks < 7) {
            int k = (ks + 1) * 16;
            wmma::load_matrix_sync(af[nxt][0], as + (size_t)r0 * LDH + k, LDH);
            wmma::load_matrix_sync(af[nxt][1], as + (size_t)(r0 + 16) * LDH + k, LDH);
            wmma::load_matrix_sync(bf[nxt][0], bs + (size_t)k * LDH + c0, LDH);
            wmma::load_matrix_sync(bf[nxt][1], bs + (size_t)k * LDH + c0 + 16, LDH);
        }
#pragma unroll
        for (int i = 0; i < 2; i++)
#pragma unroll
            for (int j = 0; j < 2; j++)
                wmma::mma_sync(acc[i][j], af[cur][i], bf[cur][j], acc[i][j]);
    }
}

// ---------------------------------------------------------------------------
// smem layout (bytes)
// ---------------------------------------------------------------------------
#define SM_W1H   0                      // half[128*LDH] 34816
#define SM_W2H   34816
#define SM_XH    69632
#define SM_TH    104448
#define SM_STAGE 139264                 // f32[128][128] = 65536
#define SM_W1R   204800                 // f32[128]
#define SM_B1    205312
#define SM_B2    205824
#define SM_AGG   206336
#define SM_IOTA  206848                 // f32[256]
#define SM_TOTAL 207872

// issue the fp32 h-tile load for this GROUP's 32 rows into stage
__device__ __forceinline__ void issue_stage_g(float* stagef, const float* h,
                                              int base, int n_nodes,
                                              int g, int wtid) {
#pragma unroll
    for (int t = 0; t < 8; t++) {
        int idx = wtid + t * 128;              // 0..1023: 32 rows x 32 float4
        int m = g * 32 + (idx >> 5);
        int c4 = (idx & 31) << 2;
        int gn = base + m;
        int ok = (gn < n_nodes);
        const float* src = h + (size_t)(ok ? gn : 0) * HID + c4;
        cp_async16(&stagef[m * HID + c4], src, ok ? 16 : 0);
    }
    cp_commit();
}

// ---------------------------------------------------------------------------
// Single fused kernel: scatter-add (grid-strided, all CTAs) -> grid spin
// barrier (all CTAs resident: grid <= #SMs, 1 CTA/SM by smem) -> tiled MLP.
//   agg = segment_sum(dist, row)/100
//   t = silu(h@W1[:128] + agg*W1[128] + b1);  out = h + t@W2 + b2
// 4 independent 4-warp pipelines per CTA (named barriers), fp16 TC,
// fp32 accum, residual from global h, cp.async stage pipeline.
// ---------------------------------------------------------------------------
__global__ void __launch_bounds__(THREADS, 1)
fused_kernel(const float* __restrict__ h,
             const int* __restrict__ edges_i32,
             const float* __restrict__ dist, int E,
             const float* __restrict__ W1, const float* __restrict__ b1,
             const float* __restrict__ W2, const float* __restrict__ b2,
             float* __restrict__ out, int n_nodes, int n_tiles)
{
    extern __shared__ char sm[];
    __half* w1h   = (__half*)(sm + SM_W1H);
    __half* w2h   = (__half*)(sm + SM_W2H);
    __half* xh    = (__half*)(sm + SM_XH);
    __half* th    = (__half*)(sm + SM_TH);
    float*  stagef = (float*)(sm + SM_STAGE);
    float*  w1r   = (float*)(sm + SM_W1R);
    float*  b1s   = (float*)(sm + SM_B1);
    float*  b2s   = (float*)(sm + SM_B2);
    float*  sagg  = (float*)(sm + SM_AGG);
    float*  iota  = (float*)(sm + SM_IOTA);

    const int tid  = threadIdx.x;
    const int warp = tid >> 5;
    const int g    = warp >> 2;          // row group 0..3 (owns rows 32g..+31)
    const int wtid = tid & 127;
    const int bid  = g + 1;
    const int r0   = g * 32;
    const int c0   = (warp & 3) * 32;

    // ---- prologue: start streaming tile 0's h rows (independent of agg) ----
    if (blockIdx.x < n_tiles)
        issue_stage_g(stagef, h, blockIdx.x * M_TILE, n_nodes, g, wtid);

    // ---- scatter slice: grid-strided over edge quads ----
    {
        // edge dtype probe (jax randint int64 demotes to int32 when x64 off;
        // true int64 -> odd 32-bit words all zero since indices < 50000)
        __shared__ int sstride;
        if (tid == 0) {
            bool all_zero = true;
            int probe = E < 16 ? E : 16;
            for (int j = 0; j < probe; j++)
                if (edges_i32[2 * j + 1] != 0) { all_zero = false; break; }
            sstride = all_zero ? 2 : 1;
        }
        __syncthreads();
        int stride = sstride;
        int nq = (E + 3) >> 2;
        int gstride = gridDim.x * THREADS;
        for (int q = blockIdx.x * THREADS + tid; q < nq; q += gstride) {
            int i4 = q * 4;
            if (i4 + 3 < E) {
                float4 d = __ldg((const float4*)&dist[i4]);
                int e0, e1, e2, e3;
                if (stride == 1) {
                    int4 r = __ldg((const int4*)&edges_i32[i4]);
                    e0 = r.x; e1 = r.y; e2 = r.z; e3 = r.w;
                } else {
                    int4 ra = __ldg((const int4*)&edges_i32[2 * i4]);
                    int4 rb = __ldg((const int4*)&edges_i32[2 * i4 + 4]);
                    e0 = ra.x; e1 = ra.z; e2 = rb.x; e3 = rb.z;
                }
                atomicAdd(&g_agg[e0], d.x);
                atomicAdd(&g_agg[e1], d.y);
                atomicAdd(&g_agg[e2], d.z);
                atomicAdd(&g_agg[e3], d.w);
            } else {
                for (int j = i4; j < E; j++)
                    atomicAdd(&g_agg[edges_i32[(long long)j * stride]], dist[j]);
            }
        }
    }

    // ---- stage weights (fp16) + vectors (fp32), overlaps other CTAs' scatter ----
    for (int idx = tid; idx < 128 * 32; idx += THREADS) {
        int k = idx >> 5, c4 = (idx & 31) << 2;
        float4 v1 = __ldg((const float4*)&W1[k * HID + c4]);
        float4 v2 = __ldg((const float4*)&W2[k * HID + c4]);
        uint2 pk, qk;
        pk.x = packh2f(v1.x, v1.y);
        pk.y = packh2f(v1.z, v1.w);
        qk.x = packh2f(v2.x, v2.y);
        qk.y = packh2f(v2.z, v2.w);
        *reinterpret_cast<uint2*>(&w1h[(size_t)k * LDH + c4]) = pk;
        *reinterpret_cast<uint2*>(&w2h[(size_t)k * LDH + c4]) = qk;
    }
    if (tid < 32) {
        *(float4*)&w1r[tid * 4] = __ldg((const float4*)&W1[128 * HID + tid * 4]);
        *(float4*)&b1s[tid * 4] = __ldg((const float4*)&b1[tid * 4]);
        *(float4*)&b2s[tid * 4] = __ldg((const float4*)&b2[tid * 4]);
    }
    if (tid < 256) iota[tid] = (float)tid;
    __syncthreads();   // CTA's scatter + staging done

    // ---- grid-wide spin barrier (monotonic ticket; replay-safe) ----
    if (tid == 0) {
        __threadfence();                         // publish this CTA's atomics
        unsigned my = atomicAdd(&g_sync, 1u);
        unsigned target = my - (my % gridDim.x) + gridDim.x;
        volatile unsigned* vs = &g_sync;
        while (*vs < target) { }
        __threadfence();                         // acquire all CTAs' atomics
    }
    __syncthreads();

    // decode accumulator fragment layout once (layout-agnostic)
    int dr[FragC::num_elements], dc[FragC::num_elements];
    {
        FragC idxf;
        wmma::load_matrix_sync(idxf, iota, 16, wmma::mem_row_major);
#pragma unroll
        for (int e = 0; e < idxf.num_elements; e++) {
            int v = __float2int_rn(idxf.x[e]);
            dr[e] = v >> 4;
            dc[e] = v & 15;
        }
    }

    for (int tile = blockIdx.x; tile < n_tiles; tile += gridDim.x) {
        const int base = tile * M_TILE;
        const int next = tile + gridDim.x;
        const bool full = (base + M_TILE <= n_nodes);

        cp_wait0();
        bar_group(bid);   // stage rows ready; prev tile th/xh reads complete

        // ---- convert group's stage rows (fp32) -> xh (fp16); agg slice ----
#pragma unroll
        for (int t = 0; t < 8; t++) {
            int idx = wtid + t * 128;
            int m = r0 + (idx >> 5), c4 = (idx & 31) << 2;
            float4 v = *(const float4*)&stagef[m * HID + c4];
            uint2 pk;
            pk.x = packh2f(v.x, v.y);
            pk.y = packh2f(v.z, v.w);
            *reinterpret_cast<uint2*>(&xh[(size_t)m * LDH + c4]) = pk;
        }
        if (wtid < 32) {
            int gn = base + r0 + wtid;
            float a = 0.f;
            if (gn < n_nodes) { a = g_agg[gn] * 0.01f; g_agg[gn] = 0.f; }
            sagg[r0 + wtid] = a;
        }
        bar_group(bid);   // xh visible; stage fully consumed by this group

        // ---- stream next tile's group rows into stage (deep overlap) ----
        if (next < n_tiles) issue_stage_g(stagef, h, next * M_TILE, n_nodes, g, wtid);

        // ---- GEMM1: D1 = X[group rows] @ W1[:128] ----
        FragC acc[2][2];
#pragma unroll
        for (int i = 0; i < 2; i++)
#pragma unroll
            for (int j = 0; j < 2; j++) wmma::fill_fragment(acc[i][j], 0.0f);
        gemm_fp16(xh, w1h, r0, c0, acc);

        // ---- epilogue1 (fp32 regs): th = silu(D1 + agg[r]*w1r[c] + b1[c]) ----
#pragma unroll
        for (int i = 0; i < 2; i++)
#pragma unroll
            for (int j = 0; j < 2; j++)
#pragma unroll
                for (int e = 0; e < FragC::num_elements; e += 2) {
                    int r = r0 + i * 16 + dr[e];
                    int c = c0 + j * 16 + dc[e];
                    bool paired = (dr[e + 1] == dr[e]) &&
                                  (dc[e + 1] == dc[e] + 1) && ((c & 1) == 0);
                    float aggv = sagg[r];
                    float v0 = acc[i][j].x[e] + aggv * w1r[c] + b1s[c];
                    if (paired) {
                        float v1 = acc[i][j].x[e + 1] + aggv * w1r[c + 1] + b1s[c + 1];
                        *(__half2*)&th[(size_t)r * LDH + c] =
                            __floats2half2_rn(silu(v0), silu(v1));
                    } else {
                        th[(size_t)r * LDH + c] = __float2half_rn(silu(v0));
                        int r1 = r0 + i * 16 + dr[e + 1];
                        int c1 = c0 + j * 16 + dc[e + 1];
                        float v1 = acc[i][j].x[e + 1] + sagg[r1] * w1r[c1] + b1s[c1];
                        th[(size_t)r1 * LDH + c1] = __float2half_rn(silu(v1));
                    }
                }

        // ---- residual straight from GLOBAL h (fp32) into acc2 ----
        FragC acc2[2][2];
        if (full) {
#pragma unroll
            for (int i = 0; i < 2; i++)
#pragma unroll
                for (int j = 0; j < 2; j++)
                    wmma::load_matrix_sync(acc2[i][j],
                        &h[(size_t)(base + r0 + i * 16) * HID + c0 + j * 16],
                        HID, wmma::mem_row_major);
        } else {
#pragma unroll
            for (int i = 0; i < 2; i++)
#pragma unroll
                for (int j = 0; j < 2; j++) wmma::fill_fragment(acc2[i][j], 0.0f);
        }

        bar_group(bid);   // group's th complete before GEMM2 reads

        // ---- GEMM2: out = residual + T[group rows] @ W2 (+ b2) ----
        gemm_fp16(th, w2h, r0, c0, acc2);

        if (full) {
#pragma unroll
            for (int i = 0; i < 2; i++)
#pragma unroll
                for (int j = 0; j < 2; j++) {
#pragma unroll
                    for (int e = 0; e < FragC::num_elements; e++)
                        acc2[i][j].x[e] += b2s[c0 + j * 16 + dc[e]];
                    wmma::store_matrix_sync(
                        &out[(size_t)(base + r0 + i * 16) * HID + c0 + j * 16],
                        acc2[i][j], HID, wmma::mem_row_major);
                }
        } else {
            // partial last tile: guarded scalar stores with residual from gmem
#pragma unroll
            for (int i = 0; i < 2; i++)
#pragma unroll
                for (int j = 0; j < 2; j++)
#pragma unroll
                    for (int e = 0; e < FragC::num_elements; e++) {
                        int gn = base + r0 + i * 16 + dr[e];
                        int c  = c0 + j * 16 + dc[e];
                        if (gn < n_nodes)
                            out[(size_t)gn * HID + c] =
                                __ldg(&h[(size_t)gn * HID + c]) +
                                acc2[i][j].x[e] + b2s[c];
                    }
        }
    }
}

// ---------------------------------------------------------------------------
extern "C" void kernel_launch(void* const* d_in, const int* in_sizes, int n_in,
                              void* d_out, int out_size) {
    const float* h    = (const float*)d_in[0];
    const int*   edg  = (const int*)  d_in[1];
    const float* dist = (const float*)d_in[2];
    const float* W1   = (const float*)d_in[9];   // W_n1 [129,128]
    const float* b1   = (const float*)d_in[10];
    const float* W2   = (const float*)d_in[11];  // W_n2 [128,128]
    const float* b2   = (const float*)d_in[12];
    float* out = (float*)d_out;

    int n_nodes = in_sizes[0] / HID;
    int E       = in_sizes[2];

    cudaFuncSetAttribute(fused_kernel,
                         cudaFuncAttributeMaxDynamicSharedMemorySize, SM_TOTAL);
    int sms = 148;
    cudaDeviceGetAttribute(&sms, cudaDevAttrMultiProcessorCount, 0);
    int n_tiles = (n_nodes + M_TILE - 1) / M_TILE;
    int grid = n_tiles < sms ? n_tiles : sms;   // all CTAs co-resident (1/SM)
    fused_kernel<<<grid, THREADS, SM_TOTAL>>>(h, edg, dist, E,
                                              W1, b1, W2, b2, out,
                                              n_nodes, n_tiles);
}

// round 17
// speedup vs baseline: 1.2899x; 1.2899x over previous
#include <cuda_runtime.h>
#include <cuda_fp16.h>
#include <mma.h>
#include <cstdint>

using namespace nvcuda;

#define HID     128
#define M_TILE  128
#define THREADS 512
#define LDH     136     // half stride: 272B ≡ 16 mod 128 -> conflict-free LDSM

// Scratch: per-node aggregate. Zero at module load; mlp re-zeroes after
// reading so the invariant holds across CUDA-graph replays.
__device__ float g_agg[65536];

// silu via single-MUFU tanh: sigmoid(x) = 0.5*tanh(x/2) + 0.5
__device__ __forceinline__ float silu(float x) {
    float t;
    asm("tanh.approx.f32 %0, %1;" : "=f"(t) : "f"(x * 0.5f));
    return x * (0.5f * t + 0.5f);
}

// ---------------------------------------------------------------------------
// scatter-add distances into g_agg[row[e]], 4 edges per thread.  PRIMARY
// kernel for PDL: signals dependents immediately so the MLP kernel's prologue
// (weights/fill, no g_agg access) overlaps the scatter.
// Edge dtype probed: jax randint int64 silently demotes to int32 when x64 is
// off; true int64 buffers have all-zero high words (indices < 50000).
// ---------------------------------------------------------------------------
__global__ void scatter_kernel(const int* __restrict__ edges_i32,
                               const float* __restrict__ dist, int E) {
    asm volatile("griddepcontrol.launch_dependents;" ::: "memory");
    __shared__ int sstride;
    if (threadIdx.x == 0) {
        bool all_zero = true;
        int probe = E < 16 ? E : 16;
        for (int j = 0; j < probe; j++)
            if (edges_i32[2 * j + 1] != 0) { all_zero = false; break; }
        sstride = all_zero ? 2 : 1;
    }
    __syncthreads();
    int stride = sstride;
    int i4 = (blockIdx.x * blockDim.x + threadIdx.x) * 4;
    if (i4 + 3 < E) {
        float4 d = __ldg((const float4*)&dist[i4]);
        int r0, r1, r2, r3;
        if (stride == 1) {
            int4 r = __ldg((const int4*)&edges_i32[i4]);
            r0 = r.x; r1 = r.y; r2 = r.z; r3 = r.w;
        } else {
            int4 ra = __ldg((const int4*)&edges_i32[2 * i4]);
            int4 rb = __ldg((const int4*)&edges_i32[2 * i4 + 4]);
            r0 = ra.x; r1 = ra.z; r2 = rb.x; r3 = rb.z;
        }
        atomicAdd(&g_agg[r0], d.x);
        atomicAdd(&g_agg[r1], d.y);
        atomicAdd(&g_agg[r2], d.z);
        atomicAdd(&g_agg[r3], d.w);
    } else {
        for (int j = i4; j < E; j++) {
            int r = edges_i32[(long long)j * stride];
            atomicAdd(&g_agg[r], dist[j]);
        }
    }
}

using FragA = wmma::fragment<wmma::matrix_a, 16, 16, 16, __half, wmma::row_major>;
using FragB = wmma::fragment<wmma::matrix_b, 16, 16, 16, __half, wmma::row_major>;
using FragC = wmma::fragment<wmma::accumulator, 16, 16, 16, float>;

// acc[2][2] += A[r0..+31][0..127] @ B[0..127][c0..+31], fp16 smem, ping-pong.
__device__ __forceinline__ void gemm_fp16(const __half* __restrict__ as,
                                          const __half* __restrict__ bs,
                                          int r0, int c0, FragC acc[2][2]) {
    FragA af[2][2];
    FragB bf[2][2];
    wmma::load_matrix_sync(af[0][0], as + (size_t)r0 * LDH, LDH);
    wmma::load_matrix_sync(af[0][1], as + (size_t)(r0 + 16) * LDH, LDH);
    wmma::load_matrix_sync(bf[0][0], bs + c0, LDH);
    wmma::load_matrix_sync(bf[0][1], bs + c0 + 16, LDH);
#pragma unroll
    for (int ks = 0; ks < 8; ks++) {
        int cur = ks & 1, nxt = cur ^ 1;
        if (ks < 7) {
            int k = (ks + 1) * 16;
            wmma::load_matrix_sync(af[nxt][0], as + (size_t)r0 * LDH + k, LDH);
            wmma::load_matrix_sync(af[nxt][1], as + (size_t)(r0 + 16) * LDH + k, LDH);
            wmma::load_matrix_sync(bf[nxt][0], bs + (size_t)k * LDH + c0, LDH);
            wmma::load_matrix_sync(bf[nxt][1], bs + (size_t)k * LDH + c0 + 16, LDH);
        }
#pragma unroll
        for (int i = 0; i < 2; i++)
#pragma unroll
            for (int j = 0; j < 2; j++)
                wmma::mma_sync(acc[i][j], af[cur][i], bf[cur][j], acc[i][j]);
    }
}

// ---------------------------------------------------------------------------
// smem layout (bytes)
// ---------------------------------------------------------------------------
#define SM_W1H   0                      // half[128*LDH] 34816
#define SM_W2H   34816
#define SM_XH    69632
#define SM_TH    104448
#define SM_STAGE 139264                 // f32[128][128] = 65536
#define SM_W1R   204800                 // f32[128]
#define SM_B1    205312
#define SM_B2    205824
#define SM_AGG   206336
#define SM_IOTA  206848                 // f32[256]
#define SM_TOTAL 207872

// cp.async 16B with zero-fill when src_sz == 0
__device__ __forceinline__ void cp_async16(void* dst_smem, const void* src, int src_sz) {
    unsigned d = (unsigned)__cvta_generic_to_shared(dst_smem);
    asm volatile("cp.async.cg.shared.global [%0], [%1], 16, %2;"
                 :: "r"(d), "l"(src), "r"(src_sz));
}
__device__ __forceinline__ void cp_commit() {
    asm volatile("cp.async.commit_group;" ::: "memory");
}
__device__ __forceinline__ void cp_wait0() {
    asm volatile("cp.async.wait_group 0;" ::: "memory");
}
// named barrier over one 128-thread row group (ids 1..4)
__device__ __forceinline__ void bar_group(int id) {
    asm volatile("bar.sync %0, 128;" :: "r"(id) : "memory");
}

// issue the fp32 h-tile load for this GROUP's 32 rows into stage
__device__ __forceinline__ void issue_stage_g(float* stagef, const float* h,
                                              int base, int n_nodes,
                                              int g, int wtid) {
#pragma unroll
    for (int t = 0; t < 8; t++) {
        int idx = wtid + t * 128;              // 0..1023: 32 rows x 32 float4
        int m = g * 32 + (idx >> 5);
        int c4 = (idx & 31) << 2;
        int gn = base + m;
        int ok = (gn < n_nodes);
        const float* src = h + (size_t)(ok ? gn : 0) * HID + c4;
        cp_async16(&stagef[m * HID + c4], src, ok ? 16 : 0);
    }
    cp_commit();
}

// ---------------------------------------------------------------------------
// Fused node MLP (fp16 TC, fp32 accum). 4 independent 4-warp pipelines per
// CTA (row groups of 32 rows), named-barrier synced. Residual streamed from
// GLOBAL h directly into accumulator fragments. SECONDARY kernel for PDL:
// prologue overlaps the scatter; griddepcontrol.wait before first agg read.
//   t = silu(h@W1k + agg*w1r + b1);  out = h + t@W2 + b2
// ---------------------------------------------------------------------------
__global__ void __launch_bounds__(THREADS, 1)
mlp_kernel(const float* __restrict__ h,
           const float* __restrict__ W1, const float* __restrict__ b1,
           const float* __restrict__ W2, const float* __restrict__ b2,
           float* __restrict__ out, int n_nodes, int n_tiles)
{
    extern __shared__ char sm[];
    __half* w1h   = (__half*)(sm + SM_W1H);
    __half* w2h   = (__half*)(sm + SM_W2H);
    __half* xh    = (__half*)(sm + SM_XH);
    __half* th    = (__half*)(sm + SM_TH);
    float*  stagef = (float*)(sm + SM_STAGE);
    float*  w1r   = (float*)(sm + SM_W1R);
    float*  b1s   = (float*)(sm + SM_B1);
    float*  b2s   = (float*)(sm + SM_B2);
    float*  sagg  = (float*)(sm + SM_AGG);
    float*  iota  = (float*)(sm + SM_IOTA);

    const int tid  = threadIdx.x;
    const int warp = tid >> 5;
    const int g    = warp >> 2;          // row group 0..3 (owns rows 32g..+31)
    const int wtid = tid & 127;
    const int bid  = g + 1;
    const int r0   = g * 32;
    const int c0   = (warp & 3) * 32;

    // ---- prologue (overlaps scatter under PDL; no g_agg access here) ----
    if (blockIdx.x < n_tiles)
        issue_stage_g(stagef, h, blockIdx.x * M_TILE, n_nodes, g, wtid);

    for (int idx = tid; idx < 128 * 32; idx += THREADS) {
        int k = idx >> 5, c4 = (idx & 31) << 2;
        float4 v1 = __ldg((const float4*)&W1[k * HID + c4]);
        float4 v2 = __ldg((const float4*)&W2[k * HID + c4]);
        __half2 p0 = __floats2half2_rn(v1.x, v1.y);
        __half2 p1 = __floats2half2_rn(v1.z, v1.w);
        __half2 q0 = __floats2half2_rn(v2.x, v2.y);
        __half2 q1 = __floats2half2_rn(v2.z, v2.w);
        uint2 pk, qk;
        pk.x = *reinterpret_cast<unsigned*>(&p0);
        pk.y = *reinterpret_cast<unsigned*>(&p1);
        qk.x = *reinterpret_cast<unsigned*>(&q0);
        qk.y = *reinterpret_cast<unsigned*>(&q1);
        *reinterpret_cast<uint2*>(&w1h[(size_t)k * LDH + c4]) = pk;
        *reinterpret_cast<uint2*>(&w2h[(size_t)k * LDH + c4]) = qk;
    }
    if (tid < 32) {
        *(float4*)&w1r[tid * 4] = __ldg((const float4*)&W1[128 * HID + tid * 4]);
        *(float4*)&b1s[tid * 4] = __ldg((const float4*)&b1[tid * 4]);
        *(float4*)&b2s[tid * 4] = __ldg((const float4*)&b2[tid * 4]);
    }
    if (tid < 256) iota[tid] = (float)tid;
    __syncthreads();   // last full-CTA sync: weights/iota visible to all

    // decode accumulator fragment layout once (layout-agnostic)
    int dr[FragC::num_elements], dc[FragC::num_elements];
    {
        FragC idxf;
        wmma::load_matrix_sync(idxf, iota, 16, wmma::mem_row_major);
#pragma unroll
        for (int e = 0; e < idxf.num_elements; e++) {
            int v = __float2int_rn(idxf.x[e]);
            dr[e] = v >> 4;
            dc[e] = v & 15;
        }
    }

    // ---- PDL join: all scatter atomics visible after this ----
    asm volatile("griddepcontrol.wait;" ::: "memory");

    for (int tile = blockIdx.x; tile < n_tiles; tile += gridDim.x) {
        const int base = tile * M_TILE;
        const int next = tile + gridDim.x;
        const bool full = (base + M_TILE <= n_nodes);

        cp_wait0();
        bar_group(bid);   // stage rows ready; prev tile th/xh reads complete

        // ---- convert group's stage rows (fp32) -> xh (fp16); agg slice ----
#pragma unroll
        for (int t = 0; t < 8; t++) {
            int idx = wtid + t * 128;
            int m = r0 + (idx >> 5), c4 = (idx & 31) << 2;
            float4 v = *(const float4*)&stagef[m * HID + c4];
            __half2 p0 = __floats2half2_rn(v.x, v.y);
            __half2 p1 = __floats2half2_rn(v.z, v.w);
            uint2 pk;
            pk.x = *reinterpret_cast<unsigned*>(&p0);
            pk.y = *reinterpret_cast<unsigned*>(&p1);
            *reinterpret_cast<uint2*>(&xh[(size_t)m * LDH + c4]) = pk;
        }
        if (wtid < 32) {
            int gn = base + r0 + wtid;
            float a = 0.f;
            if (gn < n_nodes) { a = g_agg[gn] * 0.01f; g_agg[gn] = 0.f; }
            sagg[r0 + wtid] = a;
        }
        bar_group(bid);   // xh visible; stage fully consumed by this group

        // ---- stream next tile's group rows into stage (deep overlap) ----
        if (next < n_tiles) issue_stage_g(stagef, h, next * M_TILE, n_nodes, g, wtid);

        // ---- GEMM1: D1 = X[group rows] @ W1[:128] ----
        FragC acc[2][2];
#pragma unroll
        for (int i = 0; i < 2; i++)
#pragma unroll
            for (int j = 0; j < 2; j++) wmma::fill_fragment(acc[i][j], 0.0f);
        gemm_fp16(xh, w1h, r0, c0, acc);

        // ---- epilogue1 (fp32 regs): th = silu(D1 + agg[r]*w1r[c] + b1[c]) ----
#pragma unroll
        for (int i = 0; i < 2; i++)
#pragma unroll
            for (int j = 0; j < 2; j++)
#pragma unroll
                for (int e = 0; e < FragC::num_elements; e += 2) {
                    int r = r0 + i * 16 + dr[e];
                    int c = c0 + j * 16 + dc[e];
                    bool paired = (dr[e + 1] == dr[e]) &&
                                  (dc[e + 1] == dc[e] + 1) && ((c & 1) == 0);
                    float aggv = sagg[r];
                    float v0 = acc[i][j].x[e] + aggv * w1r[c] + b1s[c];
                    if (paired) {
                        float v1 = acc[i][j].x[e + 1] + aggv * w1r[c + 1] + b1s[c + 1];
                        *(__half2*)&th[(size_t)r * LDH + c] =
                            __floats2half2_rn(silu(v0), silu(v1));
                    } else {
                        th[(size_t)r * LDH + c] = __float2half_rn(silu(v0));
                        int r1 = r0 + i * 16 + dr[e + 1];
                        int c1 = c0 + j * 16 + dc[e + 1];
                        float v1 = acc[i][j].x[e + 1] + sagg[r1] * w1r[c1] + b1s[c1];
                        th[(size_t)r1 * LDH + c1] = __float2half_rn(silu(v1));
                    }
                }

        // ---- residual straight from GLOBAL h (fp32) into acc2 ----
        FragC acc2[2][2];
        if (full) {
#pragma unroll
            for (int i = 0; i < 2; i++)
#pragma unroll
                for (int j = 0; j < 2; j++)
                    wmma::load_matrix_sync(acc2[i][j],
                        &h[(size_t)(base + r0 + i * 16) * HID + c0 + j * 16],
                        HID, wmma::mem_row_major);
        } else {
#pragma unroll
            for (int i = 0; i < 2; i++)
#pragma unroll
                for (int j = 0; j < 2; j++) wmma::fill_fragment(acc2[i][j], 0.0f);
        }

        bar_group(bid);   // group's th complete before GEMM2 reads

        // ---- GEMM2: out = residual + T[group rows] @ W2 (+ b2) ----
        gemm_fp16(th, w2h, r0, c0, acc2);

        if (full) {
#pragma unroll
            for (int i = 0; i < 2; i++)
#pragma unroll
                for (int j = 0; j < 2; j++) {
#pragma unroll
                    for (int e = 0; e < FragC::num_elements; e++)
                        acc2[i][j].x[e] += b2s[c0 + j * 16 + dc[e]];
                    wmma::store_matrix_sync(
                        &out[(size_t)(base + r0 + i * 16) * HID + c0 + j * 16],
                        acc2[i][j], HID, wmma::mem_row_major);
                }
        } else {
            // partial last tile: guarded scalar stores with residual from gmem
#pragma unroll
            for (int i = 0; i < 2; i++)
#pragma unroll
                for (int j = 0; j < 2; j++)
#pragma unroll
                    for (int e = 0; e < FragC::num_elements; e++) {
                        int gn = base + r0 + i * 16 + dr[e];
                        int c  = c0 + j * 16 + dc[e];
                        if (gn < n_nodes)
                            out[(size_t)gn * HID + c] =
                                __ldg(&h[(size_t)gn * HID + c]) +
                                acc2[i][j].x[e] + b2s[c];
                    }
        }
    }
}

// ---------------------------------------------------------------------------
extern "C" void kernel_launch(void* const* d_in, const int* in_sizes, int n_in,
                              void* d_out, int out_size) {
    const float* h    = (const float*)d_in[0];
    const int*   edg  = (const int*)  d_in[1];
    const float* dist = (const float*)d_in[2];
    const float* W1   = (const float*)d_in[9];   // W_n1 [129,128]
    const float* b1   = (const float*)d_in[10];
    const float* W2   = (const float*)d_in[11];  // W_n2 [128,128]
    const float* b2   = (const float*)d_in[12];
    float* out = (float*)d_out;

    int n_nodes = in_sizes[0] / HID;
    int E       = in_sizes[2];

    int sblocks = ((E + 3) / 4 + 255) / 256;
    scatter_kernel<<<sblocks, 256>>>(edg, dist, E);

    cudaFuncSetAttribute(mlp_kernel,
                         cudaFuncAttributeMaxDynamicSharedMemorySize, SM_TOTAL);
    int sms = 148;
    cudaDeviceGetAttribute(&sms, cudaDevAttrMultiProcessorCount, 0);
    int n_tiles = (n_nodes + M_TILE - 1) / M_TILE;
    int grid = n_tiles < sms ? n_tiles : sms;

    // PDL launch: mlp prologue overlaps the scatter; griddepcontrol.wait in
    // the kernel orders the first g_agg read after scatter completion.
    cudaLaunchConfig_t cfg = {};
    cfg.gridDim = dim3(grid, 1, 1);
    cfg.blockDim = dim3(THREADS, 1, 1);
    cfg.dynamicSmemBytes = SM_TOTAL;
    cfg.stream = 0;
    cudaLaunchAttribute attr[1];
    attr[0].id = cudaLaunchAttributeProgrammaticStreamSerialization;
    attr[0].val.programmaticStreamSerializationAllowed = 1;
    cfg.attrs = attr;
    cfg.numAttrs = 1;
    cudaError_t err = cudaLaunchKernelEx(&cfg, mlp_kernel,
                                         h, W1, b1, W2, b2, out,
                                         n_nodes, n_tiles);
    if (err != cudaSuccess) {
        // fallback: plain sequential launch (griddepcontrol.wait is a no-op
        // without a PDL edge)
        mlp_kernel<<<grid, THREADS, SM_TOTAL>>>(h, W1, b1, W2, b2, out,
                                                n_nodes, n_tiles);
    }
}